// round 1
// baseline (speedup 1.0000x reference)
#include <cuda_runtime.h>
#include <math.h>

#define BATCH 8
#define SEQ 1024
#define DIM 768
#define NH 12
#define HD 64
#define NTOK (BATCH*SEQ)          // 8192
#define EPS 1e-5f

// ---------------- scratch (allocation-free rule: __device__ globals) --------
__device__ float g_q[NTOK*DIM];
__device__ float g_k[NTOK*DIM];
__device__ float g_v[NTOK*DIM];
__device__ float g_attn[NTOK*DIM];
__device__ float g_ln[NTOK*DIM];

// ---------------- SGEMM: C[m,n] = alpha * (sum_k A[m,k]*W[n,k] + bias[n]) ---
// A: [M,K] row-major, W: [N,K] row-major (NT GEMM). M%128==0, N%128==0, K%8==0.
#define BM 128
#define BN 128
#define BK 8

__global__ void __launch_bounds__(256, 2) sgemm_nt_bias(
    const float* __restrict__ A, const float* __restrict__ W,
    const float* __restrict__ bias, float* __restrict__ C,
    int M, int N, int K, float alpha)
{
    __shared__ float As[BK][BM];
    __shared__ float Bs[BK][BN];

    const int tid = threadIdx.x;
    const int tx = tid & 15;
    const int ty = tid >> 4;
    const int bx = blockIdx.x;          // N tile
    const int by = blockIdx.y;          // M tile

    // global staging: each thread loads one float4 per operand per BK step
    const int lrow = tid >> 1;          // 0..127
    const int lk   = (tid & 1) * 4;     // 0 or 4
    const float* Ap = A + (size_t)(by*BM + lrow)*K + lk;
    const float* Wp = W + (size_t)(bx*BN + lrow)*K + lk;

    float acc[8][8] = {};

    float4 a4 = *(const float4*)(Ap);
    float4 b4 = *(const float4*)(Wp);

    for (int k0 = 0; k0 < K; k0 += BK) {
        __syncthreads();
        As[lk+0][lrow] = a4.x; As[lk+1][lrow] = a4.y;
        As[lk+2][lrow] = a4.z; As[lk+3][lrow] = a4.w;
        Bs[lk+0][lrow] = b4.x; Bs[lk+1][lrow] = b4.y;
        Bs[lk+2][lrow] = b4.z; Bs[lk+3][lrow] = b4.w;
        __syncthreads();

        if (k0 + BK < K) {              // prefetch next tile
            a4 = *(const float4*)(Ap + k0 + BK);
            b4 = *(const float4*)(Wp + k0 + BK);
        }

        #pragma unroll
        for (int kk = 0; kk < BK; ++kk) {
            float4 a0 = *(const float4*)&As[kk][ty*8];
            float4 a1 = *(const float4*)&As[kk][ty*8+4];
            float4 c0 = *(const float4*)&Bs[kk][tx*8];
            float4 c1 = *(const float4*)&Bs[kk][tx*8+4];
            float ar[8] = {a0.x,a0.y,a0.z,a0.w,a1.x,a1.y,a1.z,a1.w};
            float br[8] = {c0.x,c0.y,c0.z,c0.w,c1.x,c1.y,c1.z,c1.w};
            #pragma unroll
            for (int i = 0; i < 8; ++i)
                #pragma unroll
                for (int j = 0; j < 8; ++j)
                    acc[i][j] += ar[i]*br[j];
        }
    }

    #pragma unroll
    for (int i = 0; i < 8; ++i) {
        int row = by*BM + ty*8 + i;
        #pragma unroll
        for (int j = 0; j < 8; j += 4) {
            int col = bx*BN + tx*8 + j;
            float4 o;
            o.x = alpha*(acc[i][j+0] + bias[col+0]);
            o.y = alpha*(acc[i][j+1] + bias[col+1]);
            o.z = alpha*(acc[i][j+2] + bias[col+2]);
            o.w = alpha*(acc[i][j+3] + bias[col+3]);
            *(float4*)(C + (size_t)row*N + col) = o;
        }
    }
}

// ---------------- attention: per (b, h, 64-row q tile), flash-style --------
#define QB 64
#define KB 32

__global__ void __launch_bounds__(256) attn_kernel(
    const float* __restrict__ q, const float* __restrict__ k,
    const float* __restrict__ v, float* __restrict__ out)
{
    __shared__ float qs[HD][QB+4];   // q transposed: qs[d][row]
    __shared__ float ks[KB][HD+1];   // ks[key][d]
    __shared__ float vs[KB][HD+4];   // vs[key][d]
    __shared__ float ss[KB][QB+4];   // P transposed: ss[key][row]
    __shared__ float m_s[QB], l_s[QB], c_s[QB];

    const int tid = threadIdx.x;
    const int tx = tid & 15;         // output dim group (4 dims)
    const int ty = tid >> 4;         // row group (4 rows)
    const int qt = blockIdx.x, h = blockIdx.y, b = blockIdx.z;
    const size_t base = (size_t)b*SEQ*DIM + (size_t)h*HD;

    // load q tile, transposed
    #pragma unroll
    for (int it = 0; it < 4; ++it) {
        int f = it*256 + tid;        // 1024 float4s
        int row = f >> 4;
        int d4  = (f & 15) * 4;
        float4 t = *(const float4*)(q + base + (size_t)(qt*QB + row)*DIM + d4);
        qs[d4+0][row] = t.x; qs[d4+1][row] = t.y;
        qs[d4+2][row] = t.z; qs[d4+3][row] = t.w;
    }
    if (tid < QB) { m_s[tid] = -1e30f; l_s[tid] = 0.f; }

    float o[4][4] = {};
    __syncthreads();

    for (int kb = 0; kb < SEQ/KB; ++kb) {
        __syncthreads();             // prior iteration fully consumed ks/vs/ss
        #pragma unroll
        for (int it = 0; it < 2; ++it) {
            int f = it*256 + tid;    // 512 float4s per operand
            int r  = f >> 4;
            int d4 = (f & 15)*4;
            size_t g = base + (size_t)(kb*KB + r)*DIM + d4;
            float4 tk = *(const float4*)(k + g);
            ks[r][d4+0] = tk.x; ks[r][d4+1] = tk.y;
            ks[r][d4+2] = tk.z; ks[r][d4+3] = tk.w;
            float4 tv = *(const float4*)(v + g);
            vs[r][d4+0] = tv.x; vs[r][d4+1] = tv.y;
            vs[r][d4+2] = tv.z; vs[r][d4+3] = tv.w;
        }
        __syncthreads();

        // S = q @ k^T  (rows ty*4+i, cols tx*2+j)
        float s[4][2] = {};
        #pragma unroll
        for (int d = 0; d < HD; ++d) {
            float4 aq = *(const float4*)&qs[d][ty*4];
            float b0 = ks[tx*2+0][d];
            float b1 = ks[tx*2+1][d];
            s[0][0] += aq.x*b0; s[0][1] += aq.x*b1;
            s[1][0] += aq.y*b0; s[1][1] += aq.y*b1;
            s[2][0] += aq.z*b0; s[2][1] += aq.z*b1;
            s[3][0] += aq.w*b0; s[3][1] += aq.w*b1;
        }
        #pragma unroll
        for (int i = 0; i < 4; ++i)
            #pragma unroll
            for (int j = 0; j < 2; ++j)
                ss[tx*2+j][ty*4+i] = s[i][j];
        __syncthreads();

        // online softmax per row (64 rows, one thread each)
        if (tid < QB) {
            int r = tid;
            float m_old = m_s[r];
            float mx = m_old;
            #pragma unroll
            for (int c = 0; c < KB; ++c) mx = fmaxf(mx, ss[c][r]);
            float csc = __expf(m_old - mx);
            float sum = 0.f;
            #pragma unroll
            for (int c = 0; c < KB; ++c) {
                float p = __expf(ss[c][r] - mx);
                ss[c][r] = p;
                sum += p;
            }
            l_s[r] = l_s[r]*csc + sum;
            m_s[r] = mx;
            c_s[r] = csc;
        }
        __syncthreads();

        // rescale O, then O += P @ V
        #pragma unroll
        for (int i = 0; i < 4; ++i) {
            float cc = c_s[ty*4+i];
            #pragma unroll
            for (int j = 0; j < 4; ++j) o[i][j] *= cc;
        }
        #pragma unroll
        for (int kk = 0; kk < KB; ++kk) {
            float4 p  = *(const float4*)&ss[kk][ty*4];
            float4 vv = *(const float4*)&vs[kk][tx*4];
            o[0][0]+=p.x*vv.x; o[0][1]+=p.x*vv.y; o[0][2]+=p.x*vv.z; o[0][3]+=p.x*vv.w;
            o[1][0]+=p.y*vv.x; o[1][1]+=p.y*vv.y; o[1][2]+=p.y*vv.z; o[1][3]+=p.y*vv.w;
            o[2][0]+=p.z*vv.x; o[2][1]+=p.z*vv.y; o[2][2]+=p.z*vv.z; o[2][3]+=p.z*vv.w;
            o[3][0]+=p.w*vv.x; o[3][1]+=p.w*vv.y; o[3][2]+=p.w*vv.z; o[3][3]+=p.w*vv.w;
        }
    }

    // final normalize + store [B,N,C] layout
    #pragma unroll
    for (int i = 0; i < 4; ++i) {
        float inv = 1.f / l_s[ty*4+i];
        int row = qt*QB + ty*4 + i;
        float4 ov;
        ov.x = o[i][0]*inv; ov.y = o[i][1]*inv;
        ov.z = o[i][2]*inv; ov.w = o[i][3]*inv;
        *(float4*)(out + (size_t)b*SEQ*DIM + (size_t)row*DIM + h*HD + tx*4) = ov;
    }
}

// ---------------- layernorm over C=768, one block per token ----------------
__global__ void __launch_bounds__(256) ln_kernel(
    const float* __restrict__ inp, const float* __restrict__ gw,
    const float* __restrict__ bw, float* __restrict__ out)
{
    __shared__ float red[256];
    __shared__ float stat;
    const int t = blockIdx.x;
    const int tid = threadIdx.x;
    const float* row = inp + (size_t)t*DIM;

    float v0 = row[tid], v1 = row[tid+256], v2 = row[tid+512];
    red[tid] = v0 + v1 + v2;
    __syncthreads();
    #pragma unroll
    for (int off = 128; off > 0; off >>= 1) {
        if (tid < off) red[tid] += red[tid+off];
        __syncthreads();
    }
    if (tid == 0) stat = red[0] * (1.f/DIM);
    __syncthreads();
    const float mu = stat;
    __syncthreads();

    float d0 = v0-mu, d1 = v1-mu, d2 = v2-mu;
    red[tid] = d0*d0 + d1*d1 + d2*d2;
    __syncthreads();
    #pragma unroll
    for (int off = 128; off > 0; off >>= 1) {
        if (tid < off) red[tid] += red[tid+off];
        __syncthreads();
    }
    if (tid == 0) stat = rsqrtf(red[0]*(1.f/DIM) + EPS);
    __syncthreads();
    const float rs = stat;

    out[(size_t)t*DIM + tid      ] = d0*rs*gw[tid      ] + bw[tid      ];
    out[(size_t)t*DIM + tid + 256] = d1*rs*gw[tid + 256] + bw[tid + 256];
    out[(size_t)t*DIM + tid + 512] = d2*rs*gw[tid + 512] + bw[tid + 512];
}

// ---------------- launch ---------------------------------------------------
extern "C" void kernel_launch(void* const* d_in, const int* in_sizes, int n_in,
                              void* d_out, int out_size)
{
    const float* x    = (const float*)d_in[0];
    const float* Wq   = (const float*)d_in[1];
    const float* bq   = (const float*)d_in[2];
    const float* Wk   = (const float*)d_in[3];
    const float* bk   = (const float*)d_in[4];
    const float* Wv   = (const float*)d_in[5];
    const float* bv   = (const float*)d_in[6];
    const float* Wo   = (const float*)d_in[7];
    const float* bo   = (const float*)d_in[8];
    const float* ln_g = (const float*)d_in[9];
    const float* ln_b = (const float*)d_in[10];
    float* out = (float*)d_out;

    float *gq, *gk, *gv, *ga, *gl;
    cudaGetSymbolAddress((void**)&gq, g_q);
    cudaGetSymbolAddress((void**)&gk, g_k);
    cudaGetSymbolAddress((void**)&gv, g_v);
    cudaGetSymbolAddress((void**)&ga, g_attn);
    cudaGetSymbolAddress((void**)&gl, g_ln);

    const float scaling = 0.125f;   // HD^-0.5 = 64^-0.5

    dim3 gg(DIM/BN, NTOK/BM);       // (6, 64)
    sgemm_nt_bias<<<gg, 256>>>(x, Wq, bq, gq, NTOK, DIM, DIM, scaling);
    sgemm_nt_bias<<<gg, 256>>>(x, Wk, bk, gk, NTOK, DIM, DIM, 1.f);
    sgemm_nt_bias<<<gg, 256>>>(x, Wv, bv, gv, NTOK, DIM, DIM, 1.f);

    dim3 ag(SEQ/QB, NH, BATCH);     // (16, 12, 8)
    attn_kernel<<<ag, 256>>>(gq, gk, gv, ga);

    ln_kernel<<<NTOK, 256>>>(ga, ln_g, ln_b, gl);

    sgemm_nt_bias<<<gg, 256>>>(gl, Wo, bo, out, NTOK, DIM, DIM, 1.f);
}

// round 2
// speedup vs baseline: 2.8763x; 2.8763x over previous
#include <cuda_runtime.h>
#include <math.h>

#define BATCH 8
#define SEQ 1024
#define DIM 768
#define NH 12
#define HD 64
#define NTOK (BATCH*SEQ)          // 8192
#define EPS 1e-5f

// ---------------- scratch (allocation-free rule: __device__ globals) --------
__device__ float g_q[NTOK*DIM];
__device__ float g_k[NTOK*DIM];
__device__ float g_v[NTOK*DIM];
__device__ float g_attn[NTOK*DIM];
__device__ float g_ln[NTOK*DIM];

// ---------------- tf32 helpers ---------------------------------------------
__device__ __forceinline__ unsigned f2tf(float x) {
    unsigned r; asm("cvt.rna.tf32.f32 %0, %1;" : "=r"(r) : "f"(x)); return r;
}

// D = A(16x8) * B(8x8) + C   (tf32 inputs, fp32 accum)
__device__ __forceinline__ void mma_tf32(float* d, const unsigned* a,
                                         const unsigned* b, const float* c) {
    asm volatile(
        "mma.sync.aligned.m16n8k8.row.col.f32.tf32.tf32.f32 "
        "{%0,%1,%2,%3}, {%4,%5,%6,%7}, {%8,%9}, {%10,%11,%12,%13};"
        : "=f"(d[0]), "=f"(d[1]), "=f"(d[2]), "=f"(d[3])
        : "r"(a[0]), "r"(a[1]), "r"(a[2]), "r"(a[3]),
          "r"(b[0]), "r"(b[1]),
          "f"(c[0]), "f"(c[1]), "f"(c[2]), "f"(c[3]));
}

// ---------------- GEMM (NT): C[m,n] = alpha*(sum_k A[m,k]*W[n,k] + bias[n]) -
// 256 threads = 8 warps (2 m-warps x 4 n-warps), block tile 128x128, BK=16.
#define GST 20   // padded k-stride: 20 mod 32 pattern -> conflict-free frags

__global__ void __launch_bounds__(256) gemm_tf32(
    const float* __restrict__ A, const float* __restrict__ W,
    const float* __restrict__ bias, float* __restrict__ C,
    int M, int N, int K, float alpha)
{
    __shared__ unsigned As[2][128][GST];
    __shared__ unsigned Ws[2][128][GST];

    const int tid  = threadIdx.x;
    const int lane = tid & 31;
    const int warp = tid >> 5;
    const int wm   = warp >> 2;        // 0..1 -> 64 rows
    const int wn   = warp & 3;         // 0..3 -> 32 cols
    const int bx   = blockIdx.x;
    const int by   = blockIdx.y;

    const int g  = lane >> 2;          // groupID
    const int t  = lane & 3;           // thread-in-group

    // global staging: r0 in [0,64), kc in {0,4,8,12}; second half rows +64
    const int r0 = tid >> 2;
    const int kc = (tid & 3) * 4;
    const float* Ap = A + (size_t)(by*128 + r0)*K + kc;
    const float* Wp = W + (size_t)(bx*128 + r0)*K + kc;

    float4 ra0 = *(const float4*)(Ap);
    float4 ra1 = *(const float4*)(Ap + (size_t)64*K);
    float4 rw0 = *(const float4*)(Wp);
    float4 rw1 = *(const float4*)(Wp + (size_t)64*K);

    float acc[4][4][4];
    #pragma unroll
    for (int mi = 0; mi < 4; ++mi)
        #pragma unroll
        for (int ni = 0; ni < 4; ++ni)
            #pragma unroll
            for (int i = 0; i < 4; ++i) acc[mi][ni][i] = 0.f;

    // stage 0 -> smem
    *(uint4*)&As[0][r0   ][kc] = make_uint4(f2tf(ra0.x), f2tf(ra0.y), f2tf(ra0.z), f2tf(ra0.w));
    *(uint4*)&As[0][r0+64][kc] = make_uint4(f2tf(ra1.x), f2tf(ra1.y), f2tf(ra1.z), f2tf(ra1.w));
    *(uint4*)&Ws[0][r0   ][kc] = make_uint4(f2tf(rw0.x), f2tf(rw0.y), f2tf(rw0.z), f2tf(rw0.w));
    *(uint4*)&Ws[0][r0+64][kc] = make_uint4(f2tf(rw1.x), f2tf(rw1.y), f2tf(rw1.z), f2tf(rw1.w));
    __syncthreads();

    const int nstage = K / 16;         // 48
    int buf = 0;
    for (int s = 0; s < nstage; ++s) {
        if (s + 1 < nstage) {
            int ko = (s + 1) * 16;
            ra0 = *(const float4*)(Ap + ko);
            ra1 = *(const float4*)(Ap + (size_t)64*K + ko);
            rw0 = *(const float4*)(Wp + ko);
            rw1 = *(const float4*)(Wp + (size_t)64*K + ko);
        }
        #pragma unroll
        for (int ks = 0; ks < 2; ++ks) {
            const int k8 = ks * 8;
            unsigned afr[4][4], bfr[4][2];
            #pragma unroll
            for (int mi = 0; mi < 4; ++mi) {
                int rr = wm*64 + mi*16 + g;
                afr[mi][0] = As[buf][rr  ][k8 + t];
                afr[mi][1] = As[buf][rr+8][k8 + t];
                afr[mi][2] = As[buf][rr  ][k8 + t + 4];
                afr[mi][3] = As[buf][rr+8][k8 + t + 4];
            }
            #pragma unroll
            for (int ni = 0; ni < 4; ++ni) {
                int cc = wn*32 + ni*8 + g;
                bfr[ni][0] = Ws[buf][cc][k8 + t];
                bfr[ni][1] = Ws[buf][cc][k8 + t + 4];
            }
            #pragma unroll
            for (int mi = 0; mi < 4; ++mi)
                #pragma unroll
                for (int ni = 0; ni < 4; ++ni)
                    mma_tf32(acc[mi][ni], afr[mi], bfr[ni], acc[mi][ni]);
        }
        if (s + 1 < nstage) {
            int nb = buf ^ 1;
            *(uint4*)&As[nb][r0   ][kc] = make_uint4(f2tf(ra0.x), f2tf(ra0.y), f2tf(ra0.z), f2tf(ra0.w));
            *(uint4*)&As[nb][r0+64][kc] = make_uint4(f2tf(ra1.x), f2tf(ra1.y), f2tf(ra1.z), f2tf(ra1.w));
            *(uint4*)&Ws[nb][r0   ][kc] = make_uint4(f2tf(rw0.x), f2tf(rw0.y), f2tf(rw0.z), f2tf(rw0.w));
            *(uint4*)&Ws[nb][r0+64][kc] = make_uint4(f2tf(rw1.x), f2tf(rw1.y), f2tf(rw1.z), f2tf(rw1.w));
        }
        buf ^= 1;
        __syncthreads();
    }

    // epilogue
    #pragma unroll
    for (int mi = 0; mi < 4; ++mi) {
        int row = by*128 + wm*64 + mi*16 + g;
        #pragma unroll
        for (int ni = 0; ni < 4; ++ni) {
            int col = bx*128 + wn*32 + ni*8 + 2*t;
            float b0 = bias[col], b1 = bias[col + 1];
            float2 v;
            v.x = alpha*(acc[mi][ni][0] + b0);
            v.y = alpha*(acc[mi][ni][1] + b1);
            *(float2*)(C + (size_t)row*N + col) = v;
            v.x = alpha*(acc[mi][ni][2] + b0);
            v.y = alpha*(acc[mi][ni][3] + b1);
            *(float2*)(C + (size_t)(row + 8)*N + col) = v;
        }
    }
}

// ---------------- flash attention on tf32 mma fragments ---------------------
// Block: 256 threads (8 warps), 128 q-rows per block, 64 keys per iteration.
// Warp w owns q-rows [16w, 16w+16). Q fragments live in registers.
// Dynamic smem: Qs[128][68] (reused as P), Ks[64][68], Vs[64][72].
#define AQB 128
#define AKB 64
#define QS_ST 68
#define VS_ST 72
#define ATTN_SMEM ((AQB*QS_ST + AKB*QS_ST + AKB*VS_ST) * 4)

__global__ void __launch_bounds__(256) attn_tf32(
    const float* __restrict__ q, const float* __restrict__ k,
    const float* __restrict__ v, float* __restrict__ out)
{
    extern __shared__ unsigned dyns[];
    unsigned (*Qs)[QS_ST] = (unsigned(*)[QS_ST])dyns;                       // also P
    unsigned (*Ks)[QS_ST] = (unsigned(*)[QS_ST])(dyns + AQB*QS_ST);
    unsigned (*Vs)[VS_ST] = (unsigned(*)[VS_ST])(dyns + AQB*QS_ST + AKB*QS_ST);

    const int tid  = threadIdx.x;
    const int lane = tid & 31;
    const int warp = tid >> 5;
    const int g    = lane >> 2;
    const int t    = lane & 3;
    const int qt = blockIdx.x, h = blockIdx.y, b = blockIdx.z;
    const size_t base = (size_t)b*SEQ*DIM + (size_t)h*HD;

    // load Q tile (128 x 64), tf32-convert into smem
    #pragma unroll
    for (int i = 0; i < 8; ++i) {
        int idx = i*256 + tid;
        int row = idx >> 4;
        int d4  = (idx & 15) * 4;
        float4 tq = *(const float4*)(q + base + (size_t)(qt*AQB + row)*DIM + d4);
        Qs[row][d4+0] = f2tf(tq.x); Qs[row][d4+1] = f2tf(tq.y);
        Qs[row][d4+2] = f2tf(tq.z); Qs[row][d4+3] = f2tf(tq.w);
    }
    __syncthreads();

    // Q fragments -> registers (8 k-steps x 4 regs)
    const int r = warp*16 + g;
    unsigned aq[8][4];
    #pragma unroll
    for (int d = 0; d < 8; ++d) {
        aq[d][0] = Qs[r  ][d*8 + t];
        aq[d][1] = Qs[r+8][d*8 + t];
        aq[d][2] = Qs[r  ][d*8 + t + 4];
        aq[d][3] = Qs[r+8][d*8 + t + 4];
    }

    float o[8][4];
    #pragma unroll
    for (int n = 0; n < 8; ++n)
        #pragma unroll
        for (int i = 0; i < 4; ++i) o[n][i] = 0.f;
    float m0 = -1e30f, m1 = -1e30f, l0 = 0.f, l1 = 0.f;

    for (int kb = 0; kb < SEQ/AKB; ++kb) {
        __syncthreads();   // prior P/V consumed; Q frags loaded (first iter)
        // load K,V block (64 x 64 each)
        #pragma unroll
        for (int i = 0; i < 4; ++i) {
            int idx = i*256 + tid;
            int row = idx >> 4;
            int d4  = (idx & 15) * 4;
            size_t gaddr = base + (size_t)(kb*AKB + row)*DIM + d4;
            float4 tk = *(const float4*)(k + gaddr);
            Ks[row][d4+0] = f2tf(tk.x); Ks[row][d4+1] = f2tf(tk.y);
            Ks[row][d4+2] = f2tf(tk.z); Ks[row][d4+3] = f2tf(tk.w);
            float4 tv = *(const float4*)(v + gaddr);
            Vs[row][d4+0] = f2tf(tv.x); Vs[row][d4+1] = f2tf(tv.y);
            Vs[row][d4+2] = f2tf(tv.z); Vs[row][d4+3] = f2tf(tv.w);
        }
        __syncthreads();

        // S = Q @ K^T : 16 rows x 64 keys per warp
        float s[8][4];
        #pragma unroll
        for (int j = 0; j < 8; ++j)
            #pragma unroll
            for (int i = 0; i < 4; ++i) s[j][i] = 0.f;
        #pragma unroll
        for (int d = 0; d < 8; ++d) {
            #pragma unroll
            for (int j = 0; j < 8; ++j) {
                unsigned bfr[2];
                bfr[0] = Ks[j*8 + g][d*8 + t];
                bfr[1] = Ks[j*8 + g][d*8 + t + 4];
                mma_tf32(s[j], aq[d], bfr, s[j]);
            }
        }

        // online softmax (rows r and r+8; stats shared across quad via shfl)
        float mx0 = -1e30f, mx1 = -1e30f;
        #pragma unroll
        for (int j = 0; j < 8; ++j) {
            mx0 = fmaxf(mx0, fmaxf(s[j][0], s[j][1]));
            mx1 = fmaxf(mx1, fmaxf(s[j][2], s[j][3]));
        }
        mx0 = fmaxf(mx0, __shfl_xor_sync(0xffffffffu, mx0, 1));
        mx0 = fmaxf(mx0, __shfl_xor_sync(0xffffffffu, mx0, 2));
        mx1 = fmaxf(mx1, __shfl_xor_sync(0xffffffffu, mx1, 1));
        mx1 = fmaxf(mx1, __shfl_xor_sync(0xffffffffu, mx1, 2));
        float nm0 = fmaxf(m0, mx0), nm1 = fmaxf(m1, mx1);
        float csc0 = __expf(m0 - nm0), csc1 = __expf(m1 - nm1);
        m0 = nm0; m1 = nm1;
        float sum0 = 0.f, sum1 = 0.f;
        #pragma unroll
        for (int j = 0; j < 8; ++j) {
            s[j][0] = __expf(s[j][0] - m0);
            s[j][1] = __expf(s[j][1] - m0);
            s[j][2] = __expf(s[j][2] - m1);
            s[j][3] = __expf(s[j][3] - m1);
            sum0 += s[j][0] + s[j][1];
            sum1 += s[j][2] + s[j][3];
        }
        sum0 += __shfl_xor_sync(0xffffffffu, sum0, 1);
        sum0 += __shfl_xor_sync(0xffffffffu, sum0, 2);
        sum1 += __shfl_xor_sync(0xffffffffu, sum1, 1);
        sum1 += __shfl_xor_sync(0xffffffffu, sum1, 2);
        l0 = l0*csc0 + sum0;
        l1 = l1*csc1 + sum1;

        // write P into Qs (safe: Q is in registers), rescale O
        #pragma unroll
        for (int j = 0; j < 8; ++j) {
            int col = j*8 + 2*t;
            Qs[r  ][col] = f2tf(s[j][0]); Qs[r  ][col+1] = f2tf(s[j][1]);
            Qs[r+8][col] = f2tf(s[j][2]); Qs[r+8][col+1] = f2tf(s[j][3]);
        }
        #pragma unroll
        for (int n = 0; n < 8; ++n) {
            o[n][0] *= csc0; o[n][1] *= csc0;
            o[n][2] *= csc1; o[n][3] *= csc1;
        }
        __syncthreads();

        // O += P @ V
        #pragma unroll
        for (int kk = 0; kk < 8; ++kk) {
            unsigned pa[4];
            pa[0] = Qs[r  ][kk*8 + t];
            pa[1] = Qs[r+8][kk*8 + t];
            pa[2] = Qs[r  ][kk*8 + t + 4];
            pa[3] = Qs[r+8][kk*8 + t + 4];
            #pragma unroll
            for (int n = 0; n < 8; ++n) {
                unsigned bv[2];
                bv[0] = Vs[kk*8 + t    ][n*8 + g];
                bv[1] = Vs[kk*8 + t + 4][n*8 + g];
                mma_tf32(o[n], pa, bv, o[n]);
            }
        }
    }

    // epilogue: normalize and store
    const float i0 = 1.f / l0, i1 = 1.f / l1;
    const int row = qt*AQB + warp*16 + g;
    #pragma unroll
    for (int n = 0; n < 8; ++n) {
        int col = h*HD + n*8 + 2*t;
        float2 v0; v0.x = o[n][0]*i0; v0.y = o[n][1]*i0;
        *(float2*)(out + (size_t)b*SEQ*DIM + (size_t)row*DIM + col) = v0;
        float2 v1; v1.x = o[n][2]*i1; v1.y = o[n][3]*i1;
        *(float2*)(out + (size_t)b*SEQ*DIM + (size_t)(row + 8)*DIM + col) = v1;
    }
}

// ---------------- layernorm over C=768, one block per token ----------------
__global__ void __launch_bounds__(256) ln_kernel(
    const float* __restrict__ inp, const float* __restrict__ gw,
    const float* __restrict__ bw, float* __restrict__ out)
{
    __shared__ float red[256];
    __shared__ float stat;
    const int tok = blockIdx.x;
    const int tid = threadIdx.x;
    const float* row = inp + (size_t)tok*DIM;

    float v0 = row[tid], v1 = row[tid+256], v2 = row[tid+512];
    red[tid] = v0 + v1 + v2;
    __syncthreads();
    #pragma unroll
    for (int off = 128; off > 0; off >>= 1) {
        if (tid < off) red[tid] += red[tid+off];
        __syncthreads();
    }
    if (tid == 0) stat = red[0] * (1.f/DIM);
    __syncthreads();
    const float mu = stat;
    __syncthreads();

    float d0 = v0-mu, d1 = v1-mu, d2 = v2-mu;
    red[tid] = d0*d0 + d1*d1 + d2*d2;
    __syncthreads();
    #pragma unroll
    for (int off = 128; off > 0; off >>= 1) {
        if (tid < off) red[tid] += red[tid+off];
        __syncthreads();
    }
    if (tid == 0) stat = rsqrtf(red[0]*(1.f/DIM) + EPS);
    __syncthreads();
    const float rs = stat;

    out[(size_t)tok*DIM + tid      ] = d0*rs*gw[tid      ] + bw[tid      ];
    out[(size_t)tok*DIM + tid + 256] = d1*rs*gw[tid + 256] + bw[tid + 256];
    out[(size_t)tok*DIM + tid + 512] = d2*rs*gw[tid + 512] + bw[tid + 512];
}

// ---------------- launch ---------------------------------------------------
extern "C" void kernel_launch(void* const* d_in, const int* in_sizes, int n_in,
                              void* d_out, int out_size)
{
    const float* x    = (const float*)d_in[0];
    const float* Wq   = (const float*)d_in[1];
    const float* bq   = (const float*)d_in[2];
    const float* Wk   = (const float*)d_in[3];
    const float* bk   = (const float*)d_in[4];
    const float* Wv   = (const float*)d_in[5];
    const float* bv   = (const float*)d_in[6];
    const float* Wo   = (const float*)d_in[7];
    const float* bo   = (const float*)d_in[8];
    const float* ln_g = (const float*)d_in[9];
    const float* ln_b = (const float*)d_in[10];
    float* out = (float*)d_out;

    float *gq, *gk, *gv, *ga, *gl;
    cudaGetSymbolAddress((void**)&gq, g_q);
    cudaGetSymbolAddress((void**)&gk, g_k);
    cudaGetSymbolAddress((void**)&gv, g_v);
    cudaGetSymbolAddress((void**)&ga, g_attn);
    cudaGetSymbolAddress((void**)&gl, g_ln);

    cudaFuncSetAttribute(attn_tf32,
                         cudaFuncAttributeMaxDynamicSharedMemorySize, ATTN_SMEM);

    const float scaling = 0.125f;   // HD^-0.5

    dim3 gg(DIM/128, NTOK/128);     // (6, 64)
    gemm_tf32<<<gg, 256>>>(x, Wq, bq, gq, NTOK, DIM, DIM, scaling);
    gemm_tf32<<<gg, 256>>>(x, Wk, bk, gk, NTOK, DIM, DIM, 1.f);
    gemm_tf32<<<gg, 256>>>(x, Wv, bv, gv, NTOK, DIM, DIM, 1.f);

    dim3 ag(SEQ/AQB, NH, BATCH);    // (8, 12, 8)
    attn_tf32<<<ag, 256, ATTN_SMEM>>>(gq, gk, gv, ga);

    ln_kernel<<<NTOK, 256>>>(ga, ln_g, ln_b, gl);

    gemm_tf32<<<gg, 256>>>(gl, Wo, bo, out, NTOK, DIM, DIM, 1.f);
}